// round 1
// baseline (speedup 1.0000x reference)
#include <cuda_runtime.h>

#define OBS_LEN 20
#define PRED_LEN 30
#define H 32
#define EMB 16
#define MLPD 64
#define NOISE 8
#define NTH 256

// ---------------- shared memory layout ----------------
struct SmemT {
    float encWx[256];     // combined (4H x 2)
    float encWhh[4096];   // (4H x H)
    float encBias[128];
    float decWx[256];
    float decWhh[4096];
    float decBias[128];
    float wq[1024], wk[1024], wv[1024], wo[1024];
    float mlp1_w[4096];   // (64 x 64)
    float mlp2_w[1536];   // (24 x 64)
    float lne_g[32], lne_b[32];
    float lnc_g[64], lnc_b[64];
    float mlp1_b[64], mlp2_b[24];
    float dec_out_w[64];  // (2 x 32)
    float noisev[8];
    float dec_out_b[2];
    float pad0[2];
    float kbuf[8][32][32];
    float vbuf[8][32][32];
};

struct Params {
    const float *rel;       // obs_traj_rel (T,N,2)
    const float *noise;     // (8)
    const float *enc_emb_w, *enc_emb_b, *enc_wih, *enc_whh, *enc_bih, *enc_bhh;
    const float *lne_g, *lne_b, *wq, *wk, *wv, *wo, *lnc_g, *lnc_b;
    const float *mlp1_w, *mlp1_b, *mlp2_w, *mlp2_b;
    const float *dec_emb_w, *dec_emb_b, *dec_wih, *dec_whh, *dec_bih, *dec_bhh;
    const float *dec_out_w, *dec_out_b;
    float *out;
    int n;
};

__device__ __forceinline__ float sigf(float x) {
    return __fdividef(1.f, 1.f + __expf(-x));
}
__device__ __forceinline__ float tanhfast(float x) {
    return fmaf(2.f, sigf(2.f * x), -1.f);
}

// One LSTM step: gates = Wx*[x0,x1] + bias + Whh*h ; update c,h in place.
__device__ __forceinline__ void lstm_step(
    float *h, float *c, float x0, float x1,
    const float *__restrict__ Wx, const float *__restrict__ Whh,
    const float *__restrict__ bias)
{
    float hn[H];
#pragma unroll
    for (int j = 0; j < H; j++) {
        float gi = fmaf(Wx[2 * j],            x0, fmaf(Wx[2 * j + 1],            x1, bias[j]));
        float gf = fmaf(Wx[2 * (32 + j)],     x0, fmaf(Wx[2 * (32 + j) + 1],     x1, bias[32 + j]));
        float gg = fmaf(Wx[2 * (64 + j)],     x0, fmaf(Wx[2 * (64 + j) + 1],     x1, bias[64 + j]));
        float go = fmaf(Wx[2 * (96 + j)],     x0, fmaf(Wx[2 * (96 + j) + 1],     x1, bias[96 + j]));
#pragma unroll
        for (int k = 0; k < H; k += 4) {
            const float4 wi = *(const float4 *)(Whh + (j)      * 32 + k);
            const float4 wf = *(const float4 *)(Whh + (j + 32) * 32 + k);
            const float4 wg = *(const float4 *)(Whh + (j + 64) * 32 + k);
            const float4 wo4 = *(const float4 *)(Whh + (j + 96) * 32 + k);
            float h0 = h[k], h1 = h[k + 1], h2 = h[k + 2], h3 = h[k + 3];
            gi = fmaf(h0, wi.x, fmaf(h1, wi.y, fmaf(h2, wi.z, fmaf(h3, wi.w, gi))));
            gf = fmaf(h0, wf.x, fmaf(h1, wf.y, fmaf(h2, wf.z, fmaf(h3, wf.w, gf))));
            gg = fmaf(h0, wg.x, fmaf(h1, wg.y, fmaf(h2, wg.z, fmaf(h3, wg.w, gg))));
            go = fmaf(h0, wo4.x, fmaf(h1, wo4.y, fmaf(h2, wo4.z, fmaf(h3, wo4.w, go))));
        }
        float cj = fmaf(sigf(gf), c[j], sigf(gi) * tanhfast(gg));
        c[j] = cj;
        hn[j] = sigf(go) * tanhfast(cj);
    }
#pragma unroll
    for (int j = 0; j < H; j++) h[j] = hn[j];
}

#define CP(dst, src, cnt)                                         \
    for (int _i = threadIdx.x; _i < (cnt); _i += NTH) (dst)[_i] = (src)[_i];

__global__ void __launch_bounds__(NTH, 1)
traj_kernel(Params p)
{
    extern __shared__ float smem_raw[];
    SmemT *s = (SmemT *)smem_raw;
    const int tid = threadIdx.x;

    // ---- stage weights into shared ----
    CP(s->encWhh, p.enc_whh, 4096);
    CP(s->decWhh, p.dec_whh, 4096);
    CP(s->wq, p.wq, 1024);
    CP(s->wk, p.wk, 1024);
    CP(s->wv, p.wv, 1024);
    CP(s->wo, p.wo, 1024);
    CP(s->mlp1_w, p.mlp1_w, 4096);
    CP(s->mlp2_w, p.mlp2_w, 1536);
    CP(s->lne_g, p.lne_g, 32);
    CP(s->lne_b, p.lne_b, 32);
    CP(s->lnc_g, p.lnc_g, 64);
    CP(s->lnc_b, p.lnc_b, 64);
    CP(s->mlp1_b, p.mlp1_b, 64);
    CP(s->mlp2_b, p.mlp2_b, 24);
    CP(s->dec_out_w, p.dec_out_w, 64);
    CP(s->dec_out_b, p.dec_out_b, 2);
    CP(s->noisev, p.noise, 8);

    // combined input weights: gates_x = (Wih @ emb_w) * x + (Wih @ emb_b + bih + bhh)
    if (tid < 128) {
        int g = tid;
        float w0 = 0.f, w1 = 0.f;
        float b = p.enc_bih[g] + p.enc_bhh[g];
#pragma unroll
        for (int e = 0; e < EMB; e++) {
            float wie = p.enc_wih[g * EMB + e];
            w0 = fmaf(wie, p.enc_emb_w[e * 2 + 0], w0);
            w1 = fmaf(wie, p.enc_emb_w[e * 2 + 1], w1);
            b = fmaf(wie, p.enc_emb_b[e], b);
        }
        s->encWx[2 * g] = w0;
        s->encWx[2 * g + 1] = w1;
        s->encBias[g] = b;
    } else {
        int g = tid - 128;
        float w0 = 0.f, w1 = 0.f;
        float b = p.dec_bih[g] + p.dec_bhh[g];
#pragma unroll
        for (int e = 0; e < EMB; e++) {
            float wie = p.dec_wih[g * EMB + e];
            w0 = fmaf(wie, p.dec_emb_w[e * 2 + 0], w0);
            w1 = fmaf(wie, p.dec_emb_w[e * 2 + 1], w1);
            b = fmaf(wie, p.dec_emb_b[e], b);
        }
        s->decWx[2 * g] = w0;
        s->decWx[2 * g + 1] = w1;
        s->decBias[g] = b;
    }
    __syncthreads();

    const int agent = blockIdx.x * NTH + tid;
    if (agent >= p.n) return;
    const int n = p.n;
    const float2 *rel2 = (const float2 *)p.rel;

    // ---------------- Encoder LSTM ----------------
    float h[H], c[H];
#pragma unroll
    for (int j = 0; j < H; j++) { h[j] = 0.f; c[j] = 0.f; }

    for (int t = 0; t < OBS_LEN; t++) {
        float2 x = __ldg(&rel2[(size_t)t * n + agent]);
        lstm_step(h, c, x.x, x.y, s->encWx, s->encWhh, s->encBias);
    }

    // LayerNorm over H
    {
        float m = 0.f;
#pragma unroll
        for (int j = 0; j < H; j++) m += h[j];
        m *= (1.f / H);
        float v = 0.f;
#pragma unroll
        for (int j = 0; j < H; j++) { float d = h[j] - m; v = fmaf(d, d, v); }
        float inv = rsqrtf(v * (1.f / H) + 1e-5f);
#pragma unroll
        for (int j = 0; j < H; j++)
            h[j] = fmaf((h[j] - m) * inv, s->lne_g[j], s->lne_b[j]);
    }

    // ---------------- Per-scene attention (warp == scene of 32 agents) ----------------
    const int warp = tid >> 5;
    const int lane = tid & 31;

    float q[H];
#pragma unroll
    for (int d = 0; d < H; d++) {
        float aq = 0.f, ak = 0.f, av = 0.f;
#pragma unroll
        for (int k = 0; k < H; k += 4) {
            const float4 wq4 = *(const float4 *)(s->wq + d * 32 + k);
            const float4 wk4 = *(const float4 *)(s->wk + d * 32 + k);
            const float4 wv4 = *(const float4 *)(s->wv + d * 32 + k);
            float h0 = h[k], h1 = h[k + 1], h2 = h[k + 2], h3 = h[k + 3];
            aq = fmaf(h0, wq4.x, fmaf(h1, wq4.y, fmaf(h2, wq4.z, fmaf(h3, wq4.w, aq))));
            ak = fmaf(h0, wk4.x, fmaf(h1, wk4.y, fmaf(h2, wk4.z, fmaf(h3, wk4.w, ak))));
            av = fmaf(h0, wv4.x, fmaf(h1, wv4.y, fmaf(h2, wv4.z, fmaf(h3, wv4.w, av))));
        }
        q[d] = aq;
        s->kbuf[warp][lane][d] = ak;
        s->vbuf[warp][lane][d] = av;
    }
    __syncwarp();

    float att[H];
#pragma unroll
    for (int hh = 0; hh < 4; hh++) {
        float sc[32];
        float mx = -1e30f;
#pragma unroll
        for (int j = 0; j < 32; j++) {
            const float4 k0 = *(const float4 *)(&s->kbuf[warp][j][hh * 8]);
            const float4 k1 = *(const float4 *)(&s->kbuf[warp][j][hh * 8 + 4]);
            float d0;
            d0 = q[hh * 8 + 0] * k0.x;
            d0 = fmaf(q[hh * 8 + 1], k0.y, d0);
            d0 = fmaf(q[hh * 8 + 2], k0.z, d0);
            d0 = fmaf(q[hh * 8 + 3], k0.w, d0);
            d0 = fmaf(q[hh * 8 + 4], k1.x, d0);
            d0 = fmaf(q[hh * 8 + 5], k1.y, d0);
            d0 = fmaf(q[hh * 8 + 6], k1.z, d0);
            d0 = fmaf(q[hh * 8 + 7], k1.w, d0);
            d0 *= 0.35355339059327373f;   // 1/sqrt(8)
            sc[j] = d0;
            mx = fmaxf(mx, d0);
        }
        float sum = 0.f;
#pragma unroll
        for (int j = 0; j < 32; j++) {
            float e = __expf(sc[j] - mx);
            sc[j] = e;
            sum += e;
        }
        float inv = __fdividef(1.f, sum);
        float a0 = 0, a1 = 0, a2 = 0, a3 = 0, a4 = 0, a5 = 0, a6 = 0, a7 = 0;
#pragma unroll
        for (int j = 0; j < 32; j++) {
            const float4 v0 = *(const float4 *)(&s->vbuf[warp][j][hh * 8]);
            const float4 v1 = *(const float4 *)(&s->vbuf[warp][j][hh * 8 + 4]);
            float pj = sc[j];
            a0 = fmaf(pj, v0.x, a0); a1 = fmaf(pj, v0.y, a1);
            a2 = fmaf(pj, v0.z, a2); a3 = fmaf(pj, v0.w, a3);
            a4 = fmaf(pj, v1.x, a4); a5 = fmaf(pj, v1.y, a5);
            a6 = fmaf(pj, v1.z, a6); a7 = fmaf(pj, v1.w, a7);
        }
        att[hh * 8 + 0] = a0 * inv; att[hh * 8 + 1] = a1 * inv;
        att[hh * 8 + 2] = a2 * inv; att[hh * 8 + 3] = a3 * inv;
        att[hh * 8 + 4] = a4 * inv; att[hh * 8 + 5] = a5 * inv;
        att[hh * 8 + 6] = a6 * inv; att[hh * 8 + 7] = a7 * inv;
    }

    // output projection wo
    float ao[H];
#pragma unroll
    for (int d = 0; d < H; d++) {
        float acc = 0.f;
#pragma unroll
        for (int k = 0; k < H; k += 4) {
            const float4 w4 = *(const float4 *)(s->wo + d * 32 + k);
            acc = fmaf(att[k],     w4.x, acc);
            acc = fmaf(att[k + 1], w4.y, acc);
            acc = fmaf(att[k + 2], w4.z, acc);
            acc = fmaf(att[k + 3], w4.w, acc);
        }
        ao[d] = acc;
    }

    // ---------------- Context LN + MLP ----------------
    float ctx[64];
#pragma unroll
    for (int j = 0; j < H; j++) { ctx[j] = h[j]; ctx[32 + j] = ao[j]; }
    {
        float m = 0.f;
#pragma unroll
        for (int j = 0; j < 64; j++) m += ctx[j];
        m *= (1.f / 64.f);
        float v = 0.f;
#pragma unroll
        for (int j = 0; j < 64; j++) { float d = ctx[j] - m; v = fmaf(d, d, v); }
        float inv = rsqrtf(v * (1.f / 64.f) + 1e-5f);
#pragma unroll
        for (int j = 0; j < 64; j++)
            ctx[j] = fmaf((ctx[j] - m) * inv, s->lnc_g[j], s->lnc_b[j]);
    }

    float y1[MLPD];
#pragma unroll
    for (int m = 0; m < MLPD; m++) {
        float acc = s->mlp1_b[m];
#pragma unroll
        for (int k = 0; k < 64; k += 4) {
            const float4 w4 = *(const float4 *)(s->mlp1_w + m * 64 + k);
            acc = fmaf(ctx[k],     w4.x, acc);
            acc = fmaf(ctx[k + 1], w4.y, acc);
            acc = fmaf(ctx[k + 2], w4.z, acc);
            acc = fmaf(ctx[k + 3], w4.w, acc);
        }
        y1[m] = (acc > 0.f) ? acc : 0.01f * acc;   // leaky relu
    }

    float dh[H], dc[H];
#pragma unroll
    for (int m = 0; m < 24; m++) {
        float acc = s->mlp2_b[m];
#pragma unroll
        for (int k = 0; k < 64; k += 4) {
            const float4 w4 = *(const float4 *)(s->mlp2_w + m * 64 + k);
            acc = fmaf(y1[k],     w4.x, acc);
            acc = fmaf(y1[k + 1], w4.y, acc);
            acc = fmaf(y1[k + 2], w4.z, acc);
            acc = fmaf(y1[k + 3], w4.w, acc);
        }
        dh[m] = (acc > 0.f) ? acc : 0.01f * acc;
    }
#pragma unroll
    for (int m = 0; m < NOISE; m++) dh[24 + m] = s->noisev[m];
#pragma unroll
    for (int j = 0; j < H; j++) dc[j] = 0.f;

    // ---------------- Decoder LSTM rollout ----------------
    float2 lr = __ldg(&rel2[(size_t)(OBS_LEN - 1) * n + agent]);
    float rx = lr.x, ry = lr.y;
    float2 *out2 = (float2 *)p.out;

    for (int t = 0; t < PRED_LEN; t++) {
        lstm_step(dh, dc, rx, ry, s->decWx, s->decWhh, s->decBias);
        float ox = s->dec_out_b[0];
        float oy = s->dec_out_b[1];
#pragma unroll
        for (int k = 0; k < H; k += 4) {
            const float4 w0 = *(const float4 *)(s->dec_out_w + k);
            const float4 w1 = *(const float4 *)(s->dec_out_w + 32 + k);
            float h0 = dh[k], h1 = dh[k + 1], h2 = dh[k + 2], h3 = dh[k + 3];
            ox = fmaf(h0, w0.x, fmaf(h1, w0.y, fmaf(h2, w0.z, fmaf(h3, w0.w, ox))));
            oy = fmaf(h0, w1.x, fmaf(h1, w1.y, fmaf(h2, w1.z, fmaf(h3, w1.w, oy))));
        }
        out2[(size_t)t * n + agent] = make_float2(ox, oy);
        rx = ox;
        ry = oy;
    }
}

extern "C" void kernel_launch(void *const *d_in, const int *in_sizes, int n_in,
                              void *d_out, int out_size)
{
    Params p;
    p.rel       = (const float *)d_in[1];   // obs_traj_rel
    p.noise     = (const float *)d_in[3];
    p.enc_emb_w = (const float *)d_in[4];
    p.enc_emb_b = (const float *)d_in[5];
    p.enc_wih   = (const float *)d_in[6];
    p.enc_whh   = (const float *)d_in[7];
    p.enc_bih   = (const float *)d_in[8];
    p.enc_bhh   = (const float *)d_in[9];
    p.lne_g     = (const float *)d_in[10];
    p.lne_b     = (const float *)d_in[11];
    p.wq        = (const float *)d_in[12];
    p.wk        = (const float *)d_in[13];
    p.wv        = (const float *)d_in[14];
    p.wo        = (const float *)d_in[15];
    p.lnc_g     = (const float *)d_in[16];
    p.lnc_b     = (const float *)d_in[17];
    p.mlp1_w    = (const float *)d_in[18];
    p.mlp1_b    = (const float *)d_in[19];
    p.mlp2_w    = (const float *)d_in[20];
    p.mlp2_b    = (const float *)d_in[21];
    p.dec_emb_w = (const float *)d_in[22];
    p.dec_emb_b = (const float *)d_in[23];
    p.dec_wih   = (const float *)d_in[24];
    p.dec_whh   = (const float *)d_in[25];
    p.dec_bih   = (const float *)d_in[26];
    p.dec_bhh   = (const float *)d_in[27];
    p.dec_out_w = (const float *)d_in[28];
    p.dec_out_b = (const float *)d_in[29];
    p.out       = (float *)d_out;

    int n = in_sizes[1] / (OBS_LEN * 2);
    p.n = n;

    cudaFuncSetAttribute(traj_kernel,
                         cudaFuncAttributeMaxDynamicSharedMemorySize,
                         (int)sizeof(SmemT));

    int grid = (n + NTH - 1) / NTH;
    traj_kernel<<<grid, NTH, sizeof(SmemT)>>>(p);
}

// round 2
// speedup vs baseline: 1.3144x; 1.3144x over previous
#include <cuda_runtime.h>

#define OBS_LEN 20
#define PRED_LEN 30
#define MAXN 131072

typedef unsigned long long u64;

// ---------------- f32x2 / MUFU helpers ----------------
__device__ __forceinline__ u64 fma2(u64 a, u64 b, u64 c) {
    u64 d;
    asm("fma.rn.f32x2 %0, %1, %2, %3;" : "=l"(d) : "l"(a), "l"(b), "l"(c));
    return d;
}
__device__ __forceinline__ u64 pack2(float lo, float hi) {
    u64 d;
    asm("mov.b64 %0, {%1, %2};" : "=l"(d) : "f"(lo), "f"(hi));
    return d;
}
__device__ __forceinline__ float2 unpack2(u64 v) {
    float2 r;
    asm("mov.b64 {%0, %1}, %2;" : "=f"(r.x), "=f"(r.y) : "l"(v));
    return r;
}
__device__ __forceinline__ float tanha(float x) {
    float r;
    asm("tanh.approx.f32 %0, %1;" : "=f"(r) : "f"(x));
    return r;
}
__device__ __forceinline__ float sigt(float x) {   // sigmoid via MUFU.TANH
    return fmaf(0.5f, tanha(0.5f * x), 0.5f);
}

// ---------------- scratch (static __device__, allocation-free) ----------------
__device__ float g_h[32 * MAXN];   // h_enc (post-LN), transposed [k][N]
__device__ float g_d[32 * MAXN];   // decoder init h,  transposed [k][N]

// ---------------- shared LSTM step (k-paired f32x2) ----------------
// hp[0..15]: h as packed consecutive pairs; hp[16] = (x0, x1)
// wxb[r] = { pack(wx0, wx1), pack(bias, 0) }   (input weights folded thru emb)
__device__ __forceinline__ void lstm_step2(u64 *hp, float *c,
                                           const float *__restrict__ whh,
                                           const ulonglong2 *__restrict__ wxb)
{
    float hn[32];
#pragma unroll 4
    for (int j = 0; j < 32; j++) {
        float gv[4];
#pragma unroll
        for (int g = 0; g < 4; g++) {
            const int r = g * 32 + j;
            const ulonglong2 *wr = (const ulonglong2 *)(whh + r * 32);
            u64 acc = 0ULL;
#pragma unroll
            for (int kk = 0; kk < 8; kk++) {
                ulonglong2 w = wr[kk];
                acc = fma2(w.x, hp[2 * kk], acc);
                acc = fma2(w.y, hp[2 * kk + 1], acc);
            }
            ulonglong2 wx = wxb[r];
            acc = fma2(wx.x, hp[16], acc);
            float2 sa = unpack2(acc);
            float2 bb = unpack2(wx.y);
            gv[g] = sa.x + sa.y + bb.x;
        }
        float ig = sigt(gv[0]);
        float fg = sigt(gv[1]);
        float gg = tanha(gv[2]);
        float og = sigt(gv[3]);
        float cj = fmaf(fg, c[j], ig * gg);
        c[j] = cj;
        hn[j] = og * tanha(cj);
    }
#pragma unroll
    for (int k = 0; k < 16; k++) hp[k] = pack2(hn[2 * k], hn[2 * k + 1]);
}

// 32-dot with row in shared, h packed in regs
__device__ __forceinline__ float dot32p(const float *__restrict__ row, const u64 *hp)
{
    const ulonglong2 *wr = (const ulonglong2 *)row;
    u64 acc = 0ULL;
#pragma unroll
    for (int kk = 0; kk < 8; kk++) {
        ulonglong2 w = wr[kk];
        acc = fma2(w.x, hp[2 * kk], acc);
        acc = fma2(w.y, hp[2 * kk + 1], acc);
    }
    float2 s = unpack2(acc);
    return s.x + s.y;
}
__device__ __forceinline__ float dot64p(const float *__restrict__ row, const u64 *hp)
{
    const ulonglong2 *wr = (const ulonglong2 *)row;
    u64 acc = 0ULL;
#pragma unroll
    for (int kk = 0; kk < 16; kk++) {
        ulonglong2 w = wr[kk];
        acc = fma2(w.x, hp[2 * kk], acc);
        acc = fma2(w.y, hp[2 * kk + 1], acc);
    }
    float2 s = unpack2(acc);
    return s.x + s.y;
}

// ================= K1: encoder LSTM + LayerNorm =================
struct EncSmem {
    float whh[4096];
    ulonglong2 wxb[128];
    float lng[32], lnb[32];
};

__global__ void __launch_bounds__(128, 3)
k_enc(const float *__restrict__ rel,
      const float *__restrict__ wih, const float *__restrict__ whh_g,
      const float *__restrict__ bih, const float *__restrict__ bhh,
      const float *__restrict__ embw, const float *__restrict__ embb,
      const float *__restrict__ lng, const float *__restrict__ lnb, int n)
{
    __shared__ EncSmem s;
    const int tid = threadIdx.x;
    for (int i = tid; i < 4096; i += 128) s.whh[i] = whh_g[i];
    {   // fold: wx = Wih @ embW (2 cols), bias = Wih @ embB + bih + bhh
        int g = tid;
        float w0 = 0.f, w1 = 0.f, b = bih[g] + bhh[g];
#pragma unroll
        for (int e = 0; e < 16; e++) {
            float wie = wih[g * 16 + e];
            w0 = fmaf(wie, embw[e * 2 + 0], w0);
            w1 = fmaf(wie, embw[e * 2 + 1], w1);
            b = fmaf(wie, embb[e], b);
        }
        s.wxb[g].x = pack2(w0, w1);
        s.wxb[g].y = pack2(b, 0.f);
    }
    if (tid < 32) { s.lng[tid] = lng[tid]; s.lnb[tid] = lnb[tid]; }
    __syncthreads();

    const int agent = blockIdx.x * 128 + tid;
    if (agent >= n) return;
    const float2 *rel2 = (const float2 *)rel;

    u64 hp[17];
    float c[32];
#pragma unroll
    for (int k = 0; k < 16; k++) hp[k] = 0ULL;
#pragma unroll
    for (int j = 0; j < 32; j++) c[j] = 0.f;

    float2 x = __ldg(&rel2[agent]);
#pragma unroll 1
    for (int t = 0; t < OBS_LEN; t++) {
        float2 xn = (t + 1 < OBS_LEN) ? __ldg(&rel2[(size_t)(t + 1) * n + agent]) : x;
        hp[16] = pack2(x.x, x.y);
        lstm_step2(hp, c, s.whh, s.wxb);
        x = xn;
    }

    // LayerNorm over H, store transposed
    float hv[32];
#pragma unroll
    for (int k = 0; k < 16; k++) {
        float2 p = unpack2(hp[k]);
        hv[2 * k] = p.x;
        hv[2 * k + 1] = p.y;
    }
    float m = 0.f;
#pragma unroll
    for (int j = 0; j < 32; j++) m += hv[j];
    m *= (1.f / 32.f);
    float v = 0.f;
#pragma unroll
    for (int j = 0; j < 32; j++) { float d = hv[j] - m; v = fmaf(d, d, v); }
    float inv = rsqrtf(v * (1.f / 32.f) + 1e-5f);
#pragma unroll
    for (int j = 0; j < 32; j++)
        g_h[(size_t)j * n + agent] = fmaf((hv[j] - m) * inv, s.lng[j], s.lnb[j]);
}

// ================= K2: attention + context LN + MLP =================
struct AttnSmem {
    float wq[1024], wk[1024], wv[1024], wo[1024];
    float mlp1[4096], mlp2[1536];
    float lncg[64], lncb[64], m1b[64], m2b[24], noi[8];
    float kbuf[8][32][40];   // pad 40: 16B-aligned rows, low bank conflict
    float vbuf[8][32][40];
};

__global__ void __launch_bounds__(256)
k_attn(const float *__restrict__ wq_g, const float *__restrict__ wk_g,
       const float *__restrict__ wv_g, const float *__restrict__ wo_g,
       const float *__restrict__ lncg, const float *__restrict__ lncb,
       const float *__restrict__ m1w, const float *__restrict__ m1b,
       const float *__restrict__ m2w, const float *__restrict__ m2b,
       const float *__restrict__ noi, int n)
{
    extern __shared__ char smem_raw[];
    AttnSmem *s = (AttnSmem *)smem_raw;
    const int tid = threadIdx.x;
#define CP(d, src, c) for (int _i = tid; _i < (c); _i += 256) (d)[_i] = (src)[_i];
    CP(s->wq, wq_g, 1024) CP(s->wk, wk_g, 1024) CP(s->wv, wv_g, 1024) CP(s->wo, wo_g, 1024)
    CP(s->mlp1, m1w, 4096) CP(s->mlp2, m2w, 1536)
    CP(s->lncg, lncg, 64) CP(s->lncb, lncb, 64)
    CP(s->m1b, m1b, 64) CP(s->m2b, m2b, 24) CP(s->noi, noi, 8)
#undef CP
    __syncthreads();

    const int agent = blockIdx.x * 256 + tid;
    if (agent >= n) return;
    const int warp = tid >> 5, lane = tid & 31;

    // load h_enc (coalesced, transposed layout)
    float hv[32];
#pragma unroll
    for (int k = 0; k < 32; k++) hv[k] = __ldg(&g_h[(size_t)k * n + agent]);
    u64 hp[16];
#pragma unroll
    for (int k = 0; k < 16; k++) hp[k] = pack2(hv[2 * k], hv[2 * k + 1]);

    // QKV projections
    float q[32];
#pragma unroll
    for (int d = 0; d < 32; d++) {
        q[d] = dot32p(s->wq + d * 32, hp);
        s->kbuf[warp][lane][d] = dot32p(s->wk + d * 32, hp);
        s->vbuf[warp][lane][d] = dot32p(s->wv + d * 32, hp);
    }
    __syncwarp();

    // 4-head attention within the warp (scene == warp, all slots valid)
    float att[32];
#pragma unroll
    for (int hh = 0; hh < 4; hh++) {
        u64 qp[4];
#pragma unroll
        for (int i = 0; i < 4; i++) qp[i] = pack2(q[hh * 8 + 2 * i], q[hh * 8 + 2 * i + 1]);
        float sc[32], mx = -1e30f;
#pragma unroll
        for (int j = 0; j < 32; j++) {
            const ulonglong2 *kr = (const ulonglong2 *)&s->kbuf[warp][j][hh * 8];
            ulonglong2 k01 = kr[0], k23 = kr[1];
            u64 acc = fma2(k01.x, qp[0], 0ULL);
            acc = fma2(k01.y, qp[1], acc);
            acc = fma2(k23.x, qp[2], acc);
            acc = fma2(k23.y, qp[3], acc);
            float2 sa = unpack2(acc);
            float d0 = (sa.x + sa.y) * 0.35355339059327373f;
            sc[j] = d0;
            mx = fmaxf(mx, d0);
        }
        float sum = 0.f;
#pragma unroll
        for (int j = 0; j < 32; j++) {
            float e = __expf(sc[j] - mx);
            sc[j] = e;
            sum += e;
        }
        float inv = __fdividef(1.f, sum);
        u64 a0 = 0, a1 = 0, a2 = 0, a3 = 0;
#pragma unroll
        for (int j = 0; j < 32; j++) {
            const ulonglong2 *vr = (const ulonglong2 *)&s->vbuf[warp][j][hh * 8];
            ulonglong2 v01 = vr[0], v23 = vr[1];
            u64 pd = pack2(sc[j], sc[j]);
            a0 = fma2(v01.x, pd, a0);
            a1 = fma2(v01.y, pd, a1);
            a2 = fma2(v23.x, pd, a2);
            a3 = fma2(v23.y, pd, a3);
        }
        float2 r0 = unpack2(a0), r1 = unpack2(a1), r2 = unpack2(a2), r3 = unpack2(a3);
        att[hh * 8 + 0] = r0.x * inv; att[hh * 8 + 1] = r0.y * inv;
        att[hh * 8 + 2] = r1.x * inv; att[hh * 8 + 3] = r1.y * inv;
        att[hh * 8 + 4] = r2.x * inv; att[hh * 8 + 5] = r2.y * inv;
        att[hh * 8 + 6] = r3.x * inv; att[hh * 8 + 7] = r3.y * inv;
    }

    // wo projection
    u64 ap[16];
#pragma unroll
    for (int k = 0; k < 16; k++) ap[k] = pack2(att[2 * k], att[2 * k + 1]);
    float ctx[64];
#pragma unroll
    for (int j = 0; j < 32; j++) ctx[j] = hv[j];
#pragma unroll
    for (int d = 0; d < 32; d++) ctx[32 + d] = dot32p(s->wo + d * 32, ap);

    // context LN
    {
        float m = 0.f;
#pragma unroll
        for (int j = 0; j < 64; j++) m += ctx[j];
        m *= (1.f / 64.f);
        float v = 0.f;
#pragma unroll
        for (int j = 0; j < 64; j++) { float d = ctx[j] - m; v = fmaf(d, d, v); }
        float inv = rsqrtf(v * (1.f / 64.f) + 1e-5f);
#pragma unroll
        for (int j = 0; j < 64; j++)
            ctx[j] = fmaf((ctx[j] - m) * inv, s->lncg[j], s->lncb[j]);
    }

    // MLP 64->64->24, LeakyReLU
    u64 cp[32];
#pragma unroll
    for (int k = 0; k < 32; k++) cp[k] = pack2(ctx[2 * k], ctx[2 * k + 1]);
    float y1[64];
#pragma unroll
    for (int m = 0; m < 64; m++) {
        float a = dot64p(s->mlp1 + m * 64, cp) + s->m1b[m];
        y1[m] = (a > 0.f) ? a : 0.01f * a;
    }
    u64 yp[32];
#pragma unroll
    for (int k = 0; k < 32; k++) yp[k] = pack2(y1[2 * k], y1[2 * k + 1]);
#pragma unroll
    for (int m = 0; m < 24; m++) {
        float a = dot64p(s->mlp2 + m * 64, yp) + s->m2b[m];
        a = (a > 0.f) ? a : 0.01f * a;
        g_d[(size_t)m * n + agent] = a;
    }
#pragma unroll
    for (int m = 0; m < 8; m++) g_d[(size_t)(24 + m) * n + agent] = s->noi[m];
}

// ================= K3: decoder LSTM rollout =================
struct DecSmem {
    float whh[4096];
    ulonglong2 wxb[128];
    float outw[64];
    float outb[2];
};

__global__ void __launch_bounds__(128, 3)
k_dec(const float *__restrict__ rel,
      const float *__restrict__ wih, const float *__restrict__ whh_g,
      const float *__restrict__ bih, const float *__restrict__ bhh,
      const float *__restrict__ embw, const float *__restrict__ embb,
      const float *__restrict__ outw, const float *__restrict__ outb,
      float *__restrict__ out, int n)
{
    __shared__ DecSmem s;
    const int tid = threadIdx.x;
    for (int i = tid; i < 4096; i += 128) s.whh[i] = whh_g[i];
    {
        int g = tid;
        float w0 = 0.f, w1 = 0.f, b = bih[g] + bhh[g];
#pragma unroll
        for (int e = 0; e < 16; e++) {
            float wie = wih[g * 16 + e];
            w0 = fmaf(wie, embw[e * 2 + 0], w0);
            w1 = fmaf(wie, embw[e * 2 + 1], w1);
            b = fmaf(wie, embb[e], b);
        }
        s.wxb[g].x = pack2(w0, w1);
        s.wxb[g].y = pack2(b, 0.f);
    }
    if (tid < 64) s.outw[tid] = outw[tid];
    if (tid < 2) s.outb[tid] = outb[tid];
    __syncthreads();

    const int agent = blockIdx.x * 128 + tid;
    if (agent >= n) return;
    const float2 *rel2 = (const float2 *)rel;
    float2 *out2 = (float2 *)out;

    u64 hp[17];
    float c[32];
#pragma unroll
    for (int k = 0; k < 16; k++) {
        float a = g_d[(size_t)(2 * k) * n + agent];
        float b = g_d[(size_t)(2 * k + 1) * n + agent];
        hp[k] = pack2(a, b);
    }
#pragma unroll
    for (int j = 0; j < 32; j++) c[j] = 0.f;

    float2 x = __ldg(&rel2[(size_t)(OBS_LEN - 1) * n + agent]);
#pragma unroll 1
    for (int t = 0; t < PRED_LEN; t++) {
        hp[16] = pack2(x.x, x.y);
        lstm_step2(hp, c, s.whh, s.wxb);
        float ox = dot32p(s.outw, hp) + s.outb[0];
        float oy = dot32p(s.outw + 32, hp) + s.outb[1];
        out2[(size_t)t * n + agent] = make_float2(ox, oy);
        x = make_float2(ox, oy);
    }
}

// ================= launch =================
extern "C" void kernel_launch(void *const *d_in, const int *in_sizes, int n_in,
                              void *d_out, int out_size)
{
    const float *rel = (const float *)d_in[1];
    const float *noise = (const float *)d_in[3];
    const float *enc_emb_w = (const float *)d_in[4];
    const float *enc_emb_b = (const float *)d_in[5];
    const float *enc_wih = (const float *)d_in[6];
    const float *enc_whh = (const float *)d_in[7];
    const float *enc_bih = (const float *)d_in[8];
    const float *enc_bhh = (const float *)d_in[9];
    const float *lne_g = (const float *)d_in[10];
    const float *lne_b = (const float *)d_in[11];
    const float *wq = (const float *)d_in[12];
    const float *wk = (const float *)d_in[13];
    const float *wv = (const float *)d_in[14];
    const float *wo = (const float *)d_in[15];
    const float *lnc_g = (const float *)d_in[16];
    const float *lnc_b = (const float *)d_in[17];
    const float *mlp1_w = (const float *)d_in[18];
    const float *mlp1_b = (const float *)d_in[19];
    const float *mlp2_w = (const float *)d_in[20];
    const float *mlp2_b = (const float *)d_in[21];
    const float *dec_emb_w = (const float *)d_in[22];
    const float *dec_emb_b = (const float *)d_in[23];
    const float *dec_wih = (const float *)d_in[24];
    const float *dec_whh = (const float *)d_in[25];
    const float *dec_bih = (const float *)d_in[26];
    const float *dec_bhh = (const float *)d_in[27];
    const float *dec_out_w = (const float *)d_in[28];
    const float *dec_out_b = (const float *)d_in[29];

    int n = in_sizes[1] / (OBS_LEN * 2);

    static bool attr_set = false;
    if (!attr_set) {
        cudaFuncSetAttribute(k_attn, cudaFuncAttributeMaxDynamicSharedMemorySize,
                             (int)sizeof(AttnSmem));
        attr_set = true;
    }

    k_enc<<<(n + 127) / 128, 128>>>(rel, enc_wih, enc_whh, enc_bih, enc_bhh,
                                    enc_emb_w, enc_emb_b, lne_g, lne_b, n);
    k_attn<<<(n + 255) / 256, 256, sizeof(AttnSmem)>>>(wq, wk, wv, wo, lnc_g, lnc_b,
                                                       mlp1_w, mlp1_b, mlp2_w, mlp2_b,
                                                       noise, n);
    k_dec<<<(n + 127) / 128, 128>>>(rel, dec_wih, dec_whh, dec_bih, dec_bhh,
                                    dec_emb_w, dec_emb_b, dec_out_w, dec_out_b,
                                    (float *)d_out, n);
}

// round 3
// speedup vs baseline: 1.5155x; 1.1530x over previous
#include <cuda_runtime.h>

#define OBS_LEN 20
#define PRED_LEN 30
#define MAXN 131072

typedef unsigned long long u64;

// ---------------- f32x2 / MUFU helpers ----------------
__device__ __forceinline__ u64 fma2(u64 a, u64 b, u64 c) {
    u64 d;
    asm("fma.rn.f32x2 %0, %1, %2, %3;" : "=l"(d) : "l"(a), "l"(b), "l"(c));
    return d;
}
__device__ __forceinline__ u64 pack2(float lo, float hi) {
    u64 d;
    asm("mov.b64 %0, {%1, %2};" : "=l"(d) : "f"(lo), "f"(hi));
    return d;
}
__device__ __forceinline__ float2 unpack2(u64 v) {
    float2 r;
    asm("mov.b64 {%0, %1}, %2;" : "=f"(r.x), "=f"(r.y) : "l"(v));
    return r;
}
__device__ __forceinline__ float hsum2(u64 v) {
    float2 s = unpack2(v);
    return s.x + s.y;
}
__device__ __forceinline__ float tanha(float x) {
    float r;
    asm("tanh.approx.f32 %0, %1;" : "=f"(r) : "f"(x));
    return r;
}
__device__ __forceinline__ float sigt(float x) {
    return fmaf(0.5f, tanha(0.5f * x), 0.5f);
}

// ---------------- scratch ----------------
__device__ float g_h[32 * MAXN];   // h_enc (post-LN), transposed [k][N]
__device__ float g_d[32 * MAXN];   // decoder init h,  transposed [k][N]

// ---------------- dual-agent LSTM step ----------------
// hpA/hpB: h packed pairs (16 u64 each). xA/xB: packed inputs.
// cA/cB: shared c state, index j*128 (+tid already applied by caller).
__device__ __forceinline__ void lstm_step_dual(
    u64 *hpA, u64 *hpB, u64 xA, u64 xB,
    const float *__restrict__ whh, const ulonglong2 *__restrict__ wxb,
    float *cA, float *cB)
{
    float hnA[32], hnB[32];
#pragma unroll 2
    for (int j = 0; j < 32; j++) {
        float gvA[4], gvB[4];
#pragma unroll
        for (int g = 0; g < 4; g++) {
            const int r = g * 32 + j;
            const ulonglong2 *wr = (const ulonglong2 *)(whh + r * 32);
            u64 aA = 0ULL, aB = 0ULL;
#pragma unroll
            for (int kk = 0; kk < 8; kk++) {
                ulonglong2 w = wr[kk];
                aA = fma2(w.x, hpA[2 * kk], aA);
                aB = fma2(w.x, hpB[2 * kk], aB);
                aA = fma2(w.y, hpA[2 * kk + 1], aA);
                aB = fma2(w.y, hpB[2 * kk + 1], aB);
            }
            ulonglong2 wx = wxb[r];
            aA = fma2(wx.x, xA, aA);
            aB = fma2(wx.x, xB, aB);
            float bb = unpack2(wx.y).x;
            gvA[g] = hsum2(aA) + bb;
            gvB[g] = hsum2(aB) + bb;
        }
        {
            float cj = fmaf(sigt(gvA[1]), cA[j * 128], sigt(gvA[0]) * tanha(gvA[2]));
            cA[j * 128] = cj;
            hnA[j] = sigt(gvA[3]) * tanha(cj);
        }
        {
            float cj = fmaf(sigt(gvB[1]), cB[j * 128], sigt(gvB[0]) * tanha(gvB[2]));
            cB[j * 128] = cj;
            hnB[j] = sigt(gvB[3]) * tanha(cj);
        }
    }
#pragma unroll
    for (int k = 0; k < 16; k++) {
        hpA[k] = pack2(hnA[2 * k], hnA[2 * k + 1]);
        hpB[k] = pack2(hnB[2 * k], hnB[2 * k + 1]);
    }
}

__device__ __forceinline__ float dot32p(const float *__restrict__ row, const u64 *hp)
{
    const ulonglong2 *wr = (const ulonglong2 *)row;
    u64 acc = 0ULL;
#pragma unroll
    for (int kk = 0; kk < 8; kk++) {
        ulonglong2 w = wr[kk];
        acc = fma2(w.x, hp[2 * kk], acc);
        acc = fma2(w.y, hp[2 * kk + 1], acc);
    }
    return hsum2(acc);
}
__device__ __forceinline__ float dot64p(const float *__restrict__ row, const u64 *hp)
{
    const ulonglong2 *wr = (const ulonglong2 *)row;
    u64 acc = 0ULL;
#pragma unroll
    for (int kk = 0; kk < 16; kk++) {
        ulonglong2 w = wr[kk];
        acc = fma2(w.x, hp[2 * kk], acc);
        acc = fma2(w.y, hp[2 * kk + 1], acc);
    }
    return hsum2(acc);
}

// smem layout helper (floats): [whh 4096][wxb 512][extra E][cA 4096][cB 4096]
#define ENC_EXTRA 64    // lng 32 + lnb 32
#define DEC_EXTRA 66    // outw 64 + outb 2
#define SM_WXB 4096
#define SM_EXTRA (SM_WXB + 512)

__device__ __forceinline__ void fold_wx(
    ulonglong2 *wxb, int g,
    const float *__restrict__ wih, const float *__restrict__ bih,
    const float *__restrict__ bhh, const float *__restrict__ embw,
    const float *__restrict__ embb)
{
    float w0 = 0.f, w1 = 0.f, b = bih[g] + bhh[g];
#pragma unroll
    for (int e = 0; e < 16; e++) {
        float wie = wih[g * 16 + e];
        w0 = fmaf(wie, embw[e * 2 + 0], w0);
        w1 = fmaf(wie, embw[e * 2 + 1], w1);
        b = fmaf(wie, embb[e], b);
    }
    wxb[g].x = pack2(w0, w1);
    wxb[g].y = pack2(b, 0.f);
}

// ================= K1: encoder LSTM + LayerNorm (2 agents/thread) =================
__global__ void __launch_bounds__(128, 3)
k_enc(const float *__restrict__ rel,
      const float *__restrict__ wih, const float *__restrict__ whh_g,
      const float *__restrict__ bih, const float *__restrict__ bhh,
      const float *__restrict__ embw, const float *__restrict__ embb,
      const float *__restrict__ lng_g, const float *__restrict__ lnb_g, int n)
{
    extern __shared__ float sm[];
    float *whh = sm;
    ulonglong2 *wxb = (ulonglong2 *)(sm + SM_WXB);
    float *lng = sm + SM_EXTRA;
    float *lnb = lng + 32;
    float *cAs = sm + SM_EXTRA + ENC_EXTRA;
    float *cBs = cAs + 4096;

    const int tid = threadIdx.x;
    for (int i = tid; i < 4096; i += 128) whh[i] = whh_g[i];
    fold_wx(wxb, tid, wih, bih, bhh, embw, embb);
    if (tid < 32) { lng[tid] = lng_g[tid]; lnb[tid] = lnb_g[tid]; }
    __syncthreads();

    const int half = n >> 1;
    const int aA = blockIdx.x * 128 + tid;
    if (aA >= half) return;
    const int aB = aA + half;
    float *cA = cAs + tid, *cB = cBs + tid;

    u64 hpA[16], hpB[16];
#pragma unroll
    for (int k = 0; k < 16; k++) { hpA[k] = 0ULL; hpB[k] = 0ULL; }
#pragma unroll
    for (int j = 0; j < 32; j++) { cA[j * 128] = 0.f; cB[j * 128] = 0.f; }

    const float2 *rel2 = (const float2 *)rel;
#pragma unroll 1
    for (int t = 0; t < OBS_LEN; t++) {
        float2 xa = __ldg(&rel2[(size_t)t * n + aA]);
        float2 xb = __ldg(&rel2[(size_t)t * n + aB]);
        lstm_step_dual(hpA, hpB, pack2(xa.x, xa.y), pack2(xb.x, xb.y),
                       whh, wxb, cA, cB);
    }

    // LayerNorm + transposed store, both agents
#pragma unroll
    for (int sel = 0; sel < 2; sel++) {
        const u64 *hp = sel ? hpB : hpA;
        const int ag = sel ? aB : aA;
        float hv[32];
#pragma unroll
        for (int k = 0; k < 16; k++) {
            float2 p = unpack2(hp[k]);
            hv[2 * k] = p.x;
            hv[2 * k + 1] = p.y;
        }
        float m = 0.f;
#pragma unroll
        for (int j = 0; j < 32; j++) m += hv[j];
        m *= (1.f / 32.f);
        float v = 0.f;
#pragma unroll
        for (int j = 0; j < 32; j++) { float d = hv[j] - m; v = fmaf(d, d, v); }
        float inv = rsqrtf(v * (1.f / 32.f) + 1e-5f);
#pragma unroll
        for (int j = 0; j < 32; j++)
            g_h[(size_t)j * n + ag] = fmaf((hv[j] - m) * inv, lng[j], lnb[j]);
    }
}

// ================= K2: attention + context LN + MLP =================
struct AttnSmem {
    float wq[1024], wk[1024], wv[1024], wo[1024];
    float mlp1[4096], mlp2[1536];
    float lncg[64], lncb[64], m1b[64], m2b[24], noi[8];
    float kbuf[8][32][40];
    float vbuf[8][32][40];
};

__global__ void __launch_bounds__(256)
k_attn(const float *__restrict__ wq_g, const float *__restrict__ wk_g,
       const float *__restrict__ wv_g, const float *__restrict__ wo_g,
       const float *__restrict__ lncg, const float *__restrict__ lncb,
       const float *__restrict__ m1w, const float *__restrict__ m1b,
       const float *__restrict__ m2w, const float *__restrict__ m2b,
       const float *__restrict__ noi, int n)
{
    extern __shared__ char smem_raw[];
    AttnSmem *s = (AttnSmem *)smem_raw;
    const int tid = threadIdx.x;
#define CP(d, src, c) for (int _i = tid; _i < (c); _i += 256) (d)[_i] = (src)[_i];
    CP(s->wq, wq_g, 1024) CP(s->wk, wk_g, 1024) CP(s->wv, wv_g, 1024) CP(s->wo, wo_g, 1024)
    CP(s->mlp1, m1w, 4096) CP(s->mlp2, m2w, 1536)
    CP(s->lncg, lncg, 64) CP(s->lncb, lncb, 64)
    CP(s->m1b, m1b, 64) CP(s->m2b, m2b, 24) CP(s->noi, noi, 8)
#undef CP
    __syncthreads();

    const int agent = blockIdx.x * 256 + tid;
    if (agent >= n) return;
    const int warp = tid >> 5, lane = tid & 31;

    float hv[32];
#pragma unroll
    for (int k = 0; k < 32; k++) hv[k] = __ldg(&g_h[(size_t)k * n + agent]);
    u64 hp[16];
#pragma unroll
    for (int k = 0; k < 16; k++) hp[k] = pack2(hv[2 * k], hv[2 * k + 1]);

    float q[32];
#pragma unroll
    for (int d = 0; d < 32; d++) {
        q[d] = dot32p(s->wq + d * 32, hp);
        s->kbuf[warp][lane][d] = dot32p(s->wk + d * 32, hp);
        s->vbuf[warp][lane][d] = dot32p(s->wv + d * 32, hp);
    }
    __syncwarp();

    float att[32];
#pragma unroll
    for (int hh = 0; hh < 4; hh++) {
        u64 qp[4];
#pragma unroll
        for (int i = 0; i < 4; i++) qp[i] = pack2(q[hh * 8 + 2 * i], q[hh * 8 + 2 * i + 1]);
        float sc[32], mx = -1e30f;
#pragma unroll
        for (int j = 0; j < 32; j++) {
            const ulonglong2 *kr = (const ulonglong2 *)&s->kbuf[warp][j][hh * 8];
            ulonglong2 k01 = kr[0], k23 = kr[1];
            u64 acc = fma2(k01.x, qp[0], 0ULL);
            acc = fma2(k01.y, qp[1], acc);
            acc = fma2(k23.x, qp[2], acc);
            acc = fma2(k23.y, qp[3], acc);
            float d0 = hsum2(acc) * 0.35355339059327373f;
            sc[j] = d0;
            mx = fmaxf(mx, d0);
        }
        float sum = 0.f;
#pragma unroll
        for (int j = 0; j < 32; j++) {
            float e = __expf(sc[j] - mx);
            sc[j] = e;
            sum += e;
        }
        float inv = __fdividef(1.f, sum);
        u64 a0 = 0, a1 = 0, a2 = 0, a3 = 0;
#pragma unroll
        for (int j = 0; j < 32; j++) {
            const ulonglong2 *vr = (const ulonglong2 *)&s->vbuf[warp][j][hh * 8];
            ulonglong2 v01 = vr[0], v23 = vr[1];
            u64 pd = pack2(sc[j], sc[j]);
            a0 = fma2(v01.x, pd, a0);
            a1 = fma2(v01.y, pd, a1);
            a2 = fma2(v23.x, pd, a2);
            a3 = fma2(v23.y, pd, a3);
        }
        float2 r0 = unpack2(a0), r1 = unpack2(a1), r2 = unpack2(a2), r3 = unpack2(a3);
        att[hh * 8 + 0] = r0.x * inv; att[hh * 8 + 1] = r0.y * inv;
        att[hh * 8 + 2] = r1.x * inv; att[hh * 8 + 3] = r1.y * inv;
        att[hh * 8 + 4] = r2.x * inv; att[hh * 8 + 5] = r2.y * inv;
        att[hh * 8 + 6] = r3.x * inv; att[hh * 8 + 7] = r3.y * inv;
    }

    u64 ap[16];
#pragma unroll
    for (int k = 0; k < 16; k++) ap[k] = pack2(att[2 * k], att[2 * k + 1]);
    float ctx[64];
#pragma unroll
    for (int j = 0; j < 32; j++) ctx[j] = hv[j];
#pragma unroll
    for (int d = 0; d < 32; d++) ctx[32 + d] = dot32p(s->wo + d * 32, ap);

    {
        float m = 0.f;
#pragma unroll
        for (int j = 0; j < 64; j++) m += ctx[j];
        m *= (1.f / 64.f);
        float v = 0.f;
#pragma unroll
        for (int j = 0; j < 64; j++) { float d = ctx[j] - m; v = fmaf(d, d, v); }
        float inv = rsqrtf(v * (1.f / 64.f) + 1e-5f);
#pragma unroll
        for (int j = 0; j < 64; j++)
            ctx[j] = fmaf((ctx[j] - m) * inv, s->lncg[j], s->lncb[j]);
    }

    u64 cp[32];
#pragma unroll
    for (int k = 0; k < 32; k++) cp[k] = pack2(ctx[2 * k], ctx[2 * k + 1]);
    float y1[64];
#pragma unroll
    for (int m = 0; m < 64; m++) {
        float a = dot64p(s->mlp1 + m * 64, cp) + s->m1b[m];
        y1[m] = (a > 0.f) ? a : 0.01f * a;
    }
    u64 yp[32];
#pragma unroll
    for (int k = 0; k < 32; k++) yp[k] = pack2(y1[2 * k], y1[2 * k + 1]);
#pragma unroll
    for (int m = 0; m < 24; m++) {
        float a = dot64p(s->mlp2 + m * 64, yp) + s->m2b[m];
        a = (a > 0.f) ? a : 0.01f * a;
        g_d[(size_t)m * n + agent] = a;
    }
#pragma unroll
    for (int m = 0; m < 8; m++) g_d[(size_t)(24 + m) * n + agent] = s->noi[m];
}

// ================= K3: decoder LSTM rollout (2 agents/thread) =================
__global__ void __launch_bounds__(128, 3)
k_dec(const float *__restrict__ rel,
      const float *__restrict__ wih, const float *__restrict__ whh_g,
      const float *__restrict__ bih, const float *__restrict__ bhh,
      const float *__restrict__ embw, const float *__restrict__ embb,
      const float *__restrict__ outw_g, const float *__restrict__ outb_g,
      float *__restrict__ out, int n)
{
    extern __shared__ float sm[];
    float *whh = sm;
    ulonglong2 *wxb = (ulonglong2 *)(sm + SM_WXB);
    float *outw = sm + SM_EXTRA;
    float *outb = outw + 64;
    float *cAs = sm + SM_EXTRA + DEC_EXTRA + 62;  // keep 16B align
    float *cBs = cAs + 4096;

    const int tid = threadIdx.x;
    for (int i = tid; i < 4096; i += 128) whh[i] = whh_g[i];
    fold_wx(wxb, tid, wih, bih, bhh, embw, embb);
    if (tid < 64) outw[tid] = outw_g[tid];
    if (tid < 2) outb[tid] = outb_g[tid];
    __syncthreads();

    const int half = n >> 1;
    const int aA = blockIdx.x * 128 + tid;
    if (aA >= half) return;
    const int aB = aA + half;
    float *cA = cAs + tid, *cB = cBs + tid;

    u64 hpA[16], hpB[16];
#pragma unroll
    for (int k = 0; k < 16; k++) {
        hpA[k] = pack2(g_d[(size_t)(2 * k) * n + aA], g_d[(size_t)(2 * k + 1) * n + aA]);
        hpB[k] = pack2(g_d[(size_t)(2 * k) * n + aB], g_d[(size_t)(2 * k + 1) * n + aB]);
    }
#pragma unroll
    for (int j = 0; j < 32; j++) { cA[j * 128] = 0.f; cB[j * 128] = 0.f; }

    const float2 *rel2 = (const float2 *)rel;
    float2 *out2 = (float2 *)out;
    float2 xa = __ldg(&rel2[(size_t)(OBS_LEN - 1) * n + aA]);
    float2 xb = __ldg(&rel2[(size_t)(OBS_LEN - 1) * n + aB]);

#pragma unroll 1
    for (int t = 0; t < PRED_LEN; t++) {
        lstm_step_dual(hpA, hpB, pack2(xa.x, xa.y), pack2(xb.x, xb.y),
                       whh, wxb, cA, cB);
        float oxA = dot32p(outw, hpA) + outb[0];
        float oyA = dot32p(outw + 32, hpA) + outb[1];
        float oxB = dot32p(outw, hpB) + outb[0];
        float oyB = dot32p(outw + 32, hpB) + outb[1];
        out2[(size_t)t * n + aA] = make_float2(oxA, oyA);
        out2[(size_t)t * n + aB] = make_float2(oxB, oyB);
        xa = make_float2(oxA, oyA);
        xb = make_float2(oxB, oyB);
    }
}

// ================= launch =================
#define ENC_SMEM ((SM_EXTRA + ENC_EXTRA + 8192) * 4)
#define DEC_SMEM ((SM_EXTRA + DEC_EXTRA + 62 + 8192) * 4)

extern "C" void kernel_launch(void *const *d_in, const int *in_sizes, int n_in,
                              void *d_out, int out_size)
{
    const float *rel = (const float *)d_in[1];
    const float *noise = (const float *)d_in[3];
    const float *enc_emb_w = (const float *)d_in[4];
    const float *enc_emb_b = (const float *)d_in[5];
    const float *enc_wih = (const float *)d_in[6];
    const float *enc_whh = (const float *)d_in[7];
    const float *enc_bih = (const float *)d_in[8];
    const float *enc_bhh = (const float *)d_in[9];
    const float *lne_g = (const float *)d_in[10];
    const float *lne_b = (const float *)d_in[11];
    const float *wq = (const float *)d_in[12];
    const float *wk = (const float *)d_in[13];
    const float *wv = (const float *)d_in[14];
    const float *wo = (const float *)d_in[15];
    const float *lnc_g = (const float *)d_in[16];
    const float *lnc_b = (const float *)d_in[17];
    const float *mlp1_w = (const float *)d_in[18];
    const float *mlp1_b = (const float *)d_in[19];
    const float *mlp2_w = (const float *)d_in[20];
    const float *mlp2_b = (const float *)d_in[21];
    const float *dec_emb_w = (const float *)d_in[22];
    const float *dec_emb_b = (const float *)d_in[23];
    const float *dec_wih = (const float *)d_in[24];
    const float *dec_whh = (const float *)d_in[25];
    const float *dec_bih = (const float *)d_in[26];
    const float *dec_bhh = (const float *)d_in[27];
    const float *dec_out_w = (const float *)d_in[28];
    const float *dec_out_b = (const float *)d_in[29];

    int n = in_sizes[1] / (OBS_LEN * 2);

    static bool attr_set = false;
    if (!attr_set) {
        cudaFuncSetAttribute(k_attn, cudaFuncAttributeMaxDynamicSharedMemorySize,
                             (int)sizeof(AttnSmem));
        cudaFuncSetAttribute(k_enc, cudaFuncAttributeMaxDynamicSharedMemorySize,
                             ENC_SMEM);
        cudaFuncSetAttribute(k_dec, cudaFuncAttributeMaxDynamicSharedMemorySize,
                             DEC_SMEM);
        attr_set = true;
    }

    int half = n >> 1;
    int gridp = (half + 127) / 128;

    k_enc<<<gridp, 128, ENC_SMEM>>>(rel, enc_wih, enc_whh, enc_bih, enc_bhh,
                                    enc_emb_w, enc_emb_b, lne_g, lne_b, n);
    k_attn<<<(n + 255) / 256, 256, sizeof(AttnSmem)>>>(wq, wk, wv, wo, lnc_g, lnc_b,
                                                       mlp1_w, mlp1_b, mlp2_w, mlp2_b,
                                                       noise, n);
    k_dec<<<gridp, 128, DEC_SMEM>>>(rel, dec_wih, dec_whh, dec_bih, dec_bhh,
                                    dec_emb_w, dec_emb_b, dec_out_w, dec_out_b,
                                    (float *)d_out, n);
}